// round 16
// baseline (speedup 1.0000x reference)
#include <cuda_runtime.h>
#include <cuda_fp16.h>
#include <cstdint>

#define NN 100000
#define NE 1600000
#define IN_CH 128
#define OUT_CH 64
#define NKSTEPS (IN_CH / 16)   // 8

// Scratch (device globals: no allocation allowed in kernel_launch).
__device__ int     g_deg[NN];
__device__ float   g_dinv[NN];
__device__ __half2 g_half[(size_t)NN * 32];   // g = (x@W)*dinv[row], fp16, 12.8 MB
__device__ unsigned long long g_scan_state[512];
__device__ int     g_row_start[NN + 1];
__device__ int     g_cursor[NN];
__device__ int     g_csr_src[NE];

// ---------------------------------------------------------------------------
// 1) degree counting, x4 REDG (no return value -> fire-and-forget).
// ---------------------------------------------------------------------------
__global__ void count_deg_kernel(const int* __restrict__ ei, int n_edges) {
    const int e4 = (blockIdx.x * blockDim.x + threadIdx.x) * 4;
    if (e4 + 3 < n_edges) {
        const int4 r = *(const int4*)(ei + e4);
        const int4 c = *(const int4*)(ei + n_edges + e4);
        if ((unsigned)r.x < NN && (unsigned)c.x < NN) atomicAdd(&g_deg[c.x], 1);
        if ((unsigned)r.y < NN && (unsigned)c.y < NN) atomicAdd(&g_deg[c.y], 1);
        if ((unsigned)r.z < NN && (unsigned)c.z < NN) atomicAdd(&g_deg[c.z], 1);
        if ((unsigned)r.w < NN && (unsigned)c.w < NN) atomicAdd(&g_deg[c.w], 1);
    } else {
        for (int e = e4; e < n_edges; e++) {
            const int row = ei[e];
            const int col = ei[n_edges + e];
            if ((unsigned)row < NN && (unsigned)col < NN)
                atomicAdd(&g_deg[col], 1);
        }
    }
}

// ---------------------------------------------------------------------------
// 1b) single-pass exclusive scan, warp-parallel decoupled lookback.
//     Writes row_start, cursor, fused dinv.
// ---------------------------------------------------------------------------
__global__ void scan_kernel(int n) {
    __shared__ int s[256];
    __shared__ int s_prefix;
    const int bid = blockIdx.x;
    const int i   = bid * 256 + threadIdx.x;
    const int v   = (i < n) ? g_deg[i] : 0;

    s[threadIdx.x] = v;
    __syncthreads();
    for (int off = 1; off < 256; off <<= 1) {
        int u = (threadIdx.x >= off) ? s[threadIdx.x - off] : 0;
        __syncthreads();
        s[threadIdx.x] += u;
        __syncthreads();
    }
    const int incl = s[threadIdx.x];
    const int agg  = s[255];

    if (threadIdx.x < 32) {
        const int lane = threadIdx.x;
        if (bid == 0) {
            if (lane == 0) {
                atomicExch(&g_scan_state[0], (2ULL << 62) | (unsigned)agg);
                s_prefix = 0;
            }
        } else {
            if (lane == 0)
                atomicExch(&g_scan_state[bid], (1ULL << 62) | (unsigned)agg);
            __syncwarp();

            int pre  = 0;
            int wend = bid;
            while (true) {
                const int idx = wend - 32 + lane;
                unsigned long long st = (idx >= 0)
                    ? atomicAdd(&g_scan_state[idx], 0ULL)
                    : (2ULL << 62);
                while ((st >> 62) == 0ULL) {
                    __nanosleep(20);
                    st = atomicAdd(&g_scan_state[idx], 0ULL);
                }
                const unsigned done = __ballot_sync(0xffffffff, (st >> 62) == 2ULL);
                int val = (idx >= 0) ? (int)(st & 0xffffffffULL) : 0;
                if (done) {
                    const int highest = 31 - __clz(done);
                    if (lane < highest) val = 0;
#pragma unroll
                    for (int d = 16; d; d >>= 1) val += __shfl_down_sync(0xffffffff, val, d);
                    pre += __shfl_sync(0xffffffff, val, 0);
                    break;
                } else {
#pragma unroll
                    for (int d = 16; d; d >>= 1) val += __shfl_down_sync(0xffffffff, val, d);
                    pre += __shfl_sync(0xffffffff, val, 0);
                    wend -= 32;
                }
            }
            if (lane == 0) {
                atomicExch(&g_scan_state[bid], (2ULL << 62) | (unsigned)(pre + agg));
                s_prefix = pre;
            }
        }
    }
    __syncthreads();

    const int excl = s_prefix + incl - v;
    if (i < n) {
        g_row_start[i] = excl;
        g_cursor[i]    = excl;
        g_dinv[i]      = rsqrtf((float)(v + 1));   // +1 self loop (fused)
        if (i == n - 1) g_row_start[n] = excl + v;
    }
}

// ---------------------------------------------------------------------------
// 1c) fill CSR (1 thread/edge, cursor atomics — measured-best variant).
// ---------------------------------------------------------------------------
__global__ void fill_csr_kernel(const int* __restrict__ ei, int n_edges) {
    int e = blockIdx.x * blockDim.x + threadIdx.x;
    if (e < n_edges) {
        int row = ei[e];
        int col = ei[n_edges + e];
        if ((unsigned)row < NN && (unsigned)col < NN) {
            int pos = atomicAdd(&g_cursor[col], 1);
            g_csr_src[pos] = row;
        }
    }
}

// ---------------------------------------------------------------------------
// 2) h = x @ W via tf32 mma.sync, 3-stage cp.async pipeline.
//    g = h * dinv[row] -> g_half (fp16).
// ---------------------------------------------------------------------------
__device__ __forceinline__ unsigned f2tf32(float f) {
    unsigned r;
    asm("cvt.rna.tf32.f32 %0, %1;" : "=r"(r) : "f"(f));
    return r;
}

__device__ __forceinline__ void mma_tf32(float c[4], const unsigned a[4],
                                         const unsigned b[2]) {
    asm volatile(
        "mma.sync.aligned.m16n8k8.row.col.f32.tf32.tf32.f32 "
        "{%0,%1,%2,%3}, {%4,%5,%6,%7}, {%8,%9}, {%0,%1,%2,%3};"
        : "+f"(c[0]), "+f"(c[1]), "+f"(c[2]), "+f"(c[3])
        : "r"(a[0]), "r"(a[1]), "r"(a[2]), "r"(a[3]), "r"(b[0]), "r"(b[1]));
}

__device__ __forceinline__ void cp16(void* smem_dst, const void* gmem_src, bool pred) {
    unsigned saddr = (unsigned)__cvta_generic_to_shared(smem_dst);
    int sz = pred ? 16 : 0;
    asm volatile("cp.async.cg.shared.global [%0], [%1], 16, %2;"
                 :: "r"(saddr), "l"(gmem_src), "r"(sz));
}
#define CP_COMMIT()  asm volatile("cp.async.commit_group;")
#define CP_WAIT(N)   asm volatile("cp.async.wait_group %0;" :: "n"(N))

#define AS_STRIDE 20
#define BS_STRIDE 68

__global__ __launch_bounds__(256) void gemm_tc_kernel(
    const float* __restrict__ x, const float* __restrict__ W, int n)
{
    __shared__ unsigned As[3][128 * AS_STRIDE];
    __shared__ unsigned Bs[3][16 * BS_STRIDE];

    const int tid  = threadIdx.x;
    const int wid  = tid >> 5;
    const int lane = tid & 31;
    const int gid  = lane >> 2;
    const int tig  = lane & 3;
    const int wm   = wid & 3;
    const int wn   = wid >> 2;
    const int m0   = blockIdx.x * 128;

    const int r0  = tid >> 2;
    const int r1  = r0 + 64;
    const int c4x = (tid & 3) * 4;
    const int rW  = tid >> 4;
    const int c4W = (tid & 15) * 4;

    auto load_stage = [&](int st, int bk) {
        const int k0 = bk * 16;
        {
            const int gr = m0 + r0;
            const bool p = gr < n;
            const float* src = x + (size_t)(p ? gr : 0) * IN_CH + k0 + c4x;
            cp16(&As[st][r0 * AS_STRIDE + c4x], src, p);
        }
        {
            const int gr = m0 + r1;
            const bool p = gr < n;
            const float* src = x + (size_t)(p ? gr : 0) * IN_CH + k0 + c4x;
            cp16(&As[st][r1 * AS_STRIDE + c4x], src, p);
        }
        cp16(&Bs[st][rW * BS_STRIDE + c4W], W + (size_t)(k0 + rW) * OUT_CH + c4W, true);
        CP_COMMIT();
    };

    float c[2][4][4];
#pragma unroll
    for (int s = 0; s < 2; s++)
#pragma unroll
        for (int t = 0; t < 4; t++)
#pragma unroll
            for (int f = 0; f < 4; f++) c[s][t][f] = 0.0f;

    load_stage(0, 0);
    load_stage(1, 1);

    for (int bk = 0; bk < NKSTEPS; bk++) {
        const int cur = bk % 3;
        if (bk + 2 < NKSTEPS) {
            load_stage((bk + 2) % 3, bk + 2);
            CP_WAIT(2);
        } else if (bk + 1 < NKSTEPS) {
            CP_WAIT(1);
        } else {
            CP_WAIT(0);
        }
        __syncthreads();

#pragma unroll
        for (int ks = 0; ks < 2; ks++) {
            const int kb = ks * 8;
            unsigned a[2][4];
#pragma unroll
            for (int s = 0; s < 2; s++) {
                const int rbase = (wm * 32 + s * 16 + gid) * AS_STRIDE;
                a[s][0] = f2tf32(__uint_as_float(As[cur][rbase + kb + tig]));
                a[s][1] = f2tf32(__uint_as_float(As[cur][rbase + 8 * AS_STRIDE + kb + tig]));
                a[s][2] = f2tf32(__uint_as_float(As[cur][rbase + kb + tig + 4]));
                a[s][3] = f2tf32(__uint_as_float(As[cur][rbase + 8 * AS_STRIDE + kb + tig + 4]));
            }
            unsigned b[4][2];
#pragma unroll
            for (int t = 0; t < 4; t++) {
                const int nb = wn * 32 + t * 8 + gid;
                b[t][0] = f2tf32(__uint_as_float(Bs[cur][(kb + tig) * BS_STRIDE + nb]));
                b[t][1] = f2tf32(__uint_as_float(Bs[cur][(kb + tig + 4) * BS_STRIDE + nb]));
            }
#pragma unroll
            for (int s = 0; s < 2; s++)
#pragma unroll
                for (int t = 0; t < 4; t++)
                    mma_tf32(c[s][t], a[s], b[t]);
        }
        __syncthreads();
    }

#pragma unroll
    for (int s = 0; s < 2; s++) {
#pragma unroll
        for (int h = 0; h < 2; h++) {
            const int row = m0 + wm * 32 + s * 16 + gid + h * 8;
            if (row < n) {
                const float di = g_dinv[row];
#pragma unroll
                for (int t = 0; t < 4; t++) {
                    const int col = wn * 32 + t * 8 + tig * 2;
                    const float vx = c[s][t][h * 2 + 0] * di;
                    const float vy = c[s][t][h * 2 + 1] * di;
                    g_half[(size_t)row * 32 + (col >> 1)] = __floats2half2_rn(vx, vy);
                }
            }
        }
    }
}

// ---------------------------------------------------------------------------
// 3) pull v2 (measured-best): one warp per node, HALF-WARP per source row,
//    uint2 per lane; float4 accumulator per lane per half; shfl_xor(16)
//    combine; lanes 0-15 write the node row.
// ---------------------------------------------------------------------------
__global__ __launch_bounds__(256) void pull_kernel(
    float* __restrict__ out, const float* __restrict__ bias, int n)
{
    const int warp = (blockIdx.x * 256 + threadIdx.x) >> 5;
    const int lane = threadIdx.x & 31;
    if (warp >= n) return;
    const int half = lane >> 4;       // 0 or 1
    const int hl   = lane & 15;       // lane in half

    const int start = g_row_start[warp];
    const int end   = g_row_start[warp + 1];

    const uint2* rows = (const uint2*)g_half;   // 16 uint2 (128 B) per row

    float4 acc = make_float4(0.f, 0.f, 0.f, 0.f);

    // self loop g[c] — half 0 only (avoid double count)
    if (half == 0) {
        uint2 raw = rows[(size_t)warp * 16 + hl];
        float2 a = __half22float2(*(__half2*)&raw.x);
        float2 b = __half22float2(*(__half2*)&raw.y);
        acc.x = a.x; acc.y = a.y; acc.z = b.x; acc.w = b.y;
    }

    for (int j = start; j < end; j += 32) {
        const int id  = (j + lane < end) ? g_csr_src[j + lane] : 0;
        const int cnt = min(32, end - j);
        for (int k = 0; k < cnt; k += 8) {
            uint2 raw[4];
#pragma unroll
            for (int u = 0; u < 4; u++) {
                const int idx = k + u * 2 + half;           // this half's edge
                const int src = __shfl_sync(0xffffffff, id, idx & 31);
                raw[u] = (idx < cnt) ? rows[(size_t)src * 16 + hl]
                                     : make_uint2(0u, 0u);
            }
#pragma unroll
            for (int u = 0; u < 4; u++) {
                float2 a = __half22float2(*(__half2*)&raw[u].x);
                float2 b = __half22float2(*(__half2*)&raw[u].y);
                acc.x += a.x; acc.y += a.y; acc.z += b.x; acc.w += b.y;
            }
        }
    }

    // combine the two halves
    acc.x += __shfl_xor_sync(0xffffffff, acc.x, 16);
    acc.y += __shfl_xor_sync(0xffffffff, acc.y, 16);
    acc.z += __shfl_xor_sync(0xffffffff, acc.z, 16);
    acc.w += __shfl_xor_sync(0xffffffff, acc.w, 16);

    if (half == 0) {
        const float di = g_dinv[warp];
        const float4 bb = ((const float4*)bias)[hl];
        float4 o;
        o.x = acc.x * di + bb.x;
        o.y = acc.y * di + bb.y;
        o.z = acc.z * di + bb.z;
        o.w = acc.w * di + bb.w;
        ((float4*)out)[(size_t)warp * 16 + hl] = o;
    }
}

// ---------------------------------------------------------------------------
extern "C" void kernel_launch(void* const* d_in, const int* in_sizes, int n_in,
                              void* d_out, int out_size)
{
    const float* x  = (const float*)d_in[0];
    const int*   ei = (const int*)d_in[1];     // int32 edge_index [2, E]
    const float* W  = (const float*)d_in[2];
    const float* b  = (const float*)d_in[3];
    float*       out = (float*)d_out;

    const int n = in_sizes[0] / IN_CH;   // 100000
    const int e = in_sizes[1] / 2;       // 1600000

    void* p = nullptr;
    cudaGetSymbolAddress(&p, g_deg);
    cudaMemsetAsync(p, 0, (size_t)n * sizeof(int));
    cudaGetSymbolAddress(&p, g_scan_state);
    cudaMemsetAsync(p, 0, 512 * sizeof(unsigned long long));

    const int e4blocks = (e / 4 + 255) / 256;
    count_deg_kernel<<<e4blocks, 256>>>(ei, e);

    const int nb = (n + 255) / 256;
    scan_kernel<<<nb, 256>>>(n);

    gemm_tc_kernel<<<(n + 127) / 128, 256>>>(x, W, n);

    fill_csr_kernel<<<(e + 255) / 256, 256>>>(ei, e);

    pull_kernel<<<(n * 32 + 255) / 256, 256>>>(out, b, n);
}

// round 17
// speedup vs baseline: 1.0622x; 1.0622x over previous
#include <cuda_runtime.h>
#include <cuda_fp16.h>
#include <cstdint>

#define NN 100000
#define NE 1600000
#define IN_CH 128
#define OUT_CH 64
#define NKSTEPS (IN_CH / 16)   // 8

// Scratch (device globals: no allocation allowed in kernel_launch).
// g_zero: deg + scan_state zeroed with ONE memset.
struct ZeroBlock {
    int deg[NN];
    unsigned long long scan_state[512];
};
__device__ ZeroBlock g_z;
__device__ float   g_dinv[NN];
__device__ __half2 g_half[(size_t)NN * 32];   // g = (x@W)*dinv[row], fp16, 12.8 MB
__device__ int     g_row_start[NN + 1];
__device__ int     g_cursor[NN];
__device__ int     g_csr_src[NE];

// ---------------------------------------------------------------------------
// 1) degree counting (1 thread/edge, plain REDG — measured-best variant).
// ---------------------------------------------------------------------------
__global__ void count_deg_kernel(const int* __restrict__ ei, int n_edges) {
    int e = blockIdx.x * blockDim.x + threadIdx.x;
    if (e < n_edges) {
        int row = ei[e];
        int col = ei[n_edges + e];
        if ((unsigned)row < NN && (unsigned)col < NN)   // must match fill guard
            atomicAdd(&g_z.deg[col], 1);
    }
}

// ---------------------------------------------------------------------------
// 1b) single-pass exclusive scan, warp-parallel decoupled lookback.
//     Writes row_start, cursor, fused dinv.
// ---------------------------------------------------------------------------
__global__ void scan_kernel(int n) {
    __shared__ int s[256];
    __shared__ int s_prefix;
    const int bid = blockIdx.x;
    const int i   = bid * 256 + threadIdx.x;
    const int v   = (i < n) ? g_z.deg[i] : 0;

    s[threadIdx.x] = v;
    __syncthreads();
    for (int off = 1; off < 256; off <<= 1) {
        int u = (threadIdx.x >= off) ? s[threadIdx.x - off] : 0;
        __syncthreads();
        s[threadIdx.x] += u;
        __syncthreads();
    }
    const int incl = s[threadIdx.x];
    const int agg  = s[255];

    if (threadIdx.x < 32) {
        const int lane = threadIdx.x;
        if (bid == 0) {
            if (lane == 0) {
                atomicExch(&g_z.scan_state[0], (2ULL << 62) | (unsigned)agg);
                s_prefix = 0;
            }
        } else {
            if (lane == 0)
                atomicExch(&g_z.scan_state[bid], (1ULL << 62) | (unsigned)agg);
            __syncwarp();

            int pre  = 0;
            int wend = bid;
            while (true) {
                const int idx = wend - 32 + lane;
                unsigned long long st = (idx >= 0)
                    ? atomicAdd(&g_z.scan_state[idx], 0ULL)
                    : (2ULL << 62);
                while ((st >> 62) == 0ULL) {
                    __nanosleep(20);
                    st = atomicAdd(&g_z.scan_state[idx], 0ULL);
                }
                const unsigned done = __ballot_sync(0xffffffff, (st >> 62) == 2ULL);
                int val = (idx >= 0) ? (int)(st & 0xffffffffULL) : 0;
                if (done) {
                    const int highest = 31 - __clz(done);
                    if (lane < highest) val = 0;
#pragma unroll
                    for (int d = 16; d; d >>= 1) val += __shfl_down_sync(0xffffffff, val, d);
                    pre += __shfl_sync(0xffffffff, val, 0);
                    break;
                } else {
#pragma unroll
                    for (int d = 16; d; d >>= 1) val += __shfl_down_sync(0xffffffff, val, d);
                    pre += __shfl_sync(0xffffffff, val, 0);
                    wend -= 32;
                }
            }
            if (lane == 0) {
                atomicExch(&g_z.scan_state[bid], (2ULL << 62) | (unsigned)(pre + agg));
                s_prefix = pre;
            }
        }
    }
    __syncthreads();

    const int excl = s_prefix + incl - v;
    if (i < n) {
        g_row_start[i] = excl;
        g_cursor[i]    = excl;
        g_dinv[i]      = rsqrtf((float)(v + 1));   // +1 self loop (fused)
        if (i == n - 1) g_row_start[n] = excl + v;
    }
}

// ---------------------------------------------------------------------------
// 1c) fill CSR (1 thread/edge, cursor atomics — measured-best variant).
// ---------------------------------------------------------------------------
__global__ void fill_csr_kernel(const int* __restrict__ ei, int n_edges) {
    int e = blockIdx.x * blockDim.x + threadIdx.x;
    if (e < n_edges) {
        int row = ei[e];
        int col = ei[n_edges + e];
        if ((unsigned)row < NN && (unsigned)col < NN) {
            int pos = atomicAdd(&g_cursor[col], 1);
            g_csr_src[pos] = row;
        }
    }
}

// ---------------------------------------------------------------------------
// 2) h = x @ W via tf32 mma.sync, 3-stage cp.async pipeline.
//    RAW f32 bits fed as tf32 operands (HW truncates low mantissa — no cvt).
//    One __syncthreads per bk. g = h * dinv[row] -> g_half (fp16).
// ---------------------------------------------------------------------------
__device__ __forceinline__ void mma_tf32(float c[4], const unsigned a[4],
                                         const unsigned b[2]) {
    asm volatile(
        "mma.sync.aligned.m16n8k8.row.col.f32.tf32.tf32.f32 "
        "{%0,%1,%2,%3}, {%4,%5,%6,%7}, {%8,%9}, {%0,%1,%2,%3};"
        : "+f"(c[0]), "+f"(c[1]), "+f"(c[2]), "+f"(c[3])
        : "r"(a[0]), "r"(a[1]), "r"(a[2]), "r"(a[3]), "r"(b[0]), "r"(b[1]));
}

__device__ __forceinline__ void cp16(void* smem_dst, const void* gmem_src, bool pred) {
    unsigned saddr = (unsigned)__cvta_generic_to_shared(smem_dst);
    int sz = pred ? 16 : 0;
    asm volatile("cp.async.cg.shared.global [%0], [%1], 16, %2;"
                 :: "r"(saddr), "l"(gmem_src), "r"(sz));
}
#define CP_COMMIT()  asm volatile("cp.async.commit_group;")
#define CP_WAIT(N)   asm volatile("cp.async.wait_group %0;" :: "n"(N))

#define AS_STRIDE 20
#define BS_STRIDE 68

__global__ __launch_bounds__(256) void gemm_tc_kernel(
    const float* __restrict__ x, const float* __restrict__ W, int n)
{
    __shared__ unsigned As[3][128 * AS_STRIDE];   // raw f32 bits (= tf32 operands)
    __shared__ unsigned Bs[3][16 * BS_STRIDE];

    const int tid  = threadIdx.x;
    const int wid  = tid >> 5;
    const int lane = tid & 31;
    const int gid  = lane >> 2;
    const int tig  = lane & 3;
    const int wm   = wid & 3;
    const int wn   = wid >> 2;
    const int m0   = blockIdx.x * 128;

    const int r0  = tid >> 2;
    const int r1  = r0 + 64;
    const int c4x = (tid & 3) * 4;
    const int rW  = tid >> 4;
    const int c4W = (tid & 15) * 4;

    auto load_stage = [&](int st, int bk) {
        const int k0 = bk * 16;
        {
            const int gr = m0 + r0;
            const bool p = gr < n;
            const float* src = x + (size_t)(p ? gr : 0) * IN_CH + k0 + c4x;
            cp16(&As[st][r0 * AS_STRIDE + c4x], src, p);
        }
        {
            const int gr = m0 + r1;
            const bool p = gr < n;
            const float* src = x + (size_t)(p ? gr : 0) * IN_CH + k0 + c4x;
            cp16(&As[st][r1 * AS_STRIDE + c4x], src, p);
        }
        cp16(&Bs[st][rW * BS_STRIDE + c4W], W + (size_t)(k0 + rW) * OUT_CH + c4W, true);
        CP_COMMIT();
    };

    float c[2][4][4];
#pragma unroll
    for (int s = 0; s < 2; s++)
#pragma unroll
        for (int t = 0; t < 4; t++)
#pragma unroll
            for (int f = 0; f < 4; f++) c[s][t][f] = 0.0f;

    load_stage(0, 0);
    load_stage(1, 1);

    for (int bk = 0; bk < NKSTEPS; bk++) {
        const int cur = bk % 3;
        if (bk + 1 < NKSTEPS) CP_WAIT(1); else CP_WAIT(0);
        __syncthreads();     // single barrier: separates prev compute from the
                             // overwrite of stage (bk+2)%3 == (bk-1)%3 below
        if (bk + 2 < NKSTEPS) load_stage((bk + 2) % 3, bk + 2);

#pragma unroll
        for (int ks = 0; ks < 2; ks++) {
            const int kb = ks * 8;
            unsigned a[2][4];
#pragma unroll
            for (int s = 0; s < 2; s++) {
                const int rbase = (wm * 32 + s * 16 + gid) * AS_STRIDE;
                a[s][0] = As[cur][rbase + kb + tig];
                a[s][1] = As[cur][rbase + 8 * AS_STRIDE + kb + tig];
                a[s][2] = As[cur][rbase + kb + tig + 4];
                a[s][3] = As[cur][rbase + 8 * AS_STRIDE + kb + tig + 4];
            }
            unsigned b[4][2];
#pragma unroll
            for (int t = 0; t < 4; t++) {
                const int nb = wn * 32 + t * 8 + gid;
                b[t][0] = Bs[cur][(kb + tig) * BS_STRIDE + nb];
                b[t][1] = Bs[cur][(kb + tig + 4) * BS_STRIDE + nb];
            }
#pragma unroll
            for (int s = 0; s < 2; s++)
#pragma unroll
                for (int t = 0; t < 4; t++)
                    mma_tf32(c[s][t], a[s], b[t]);
        }
    }

#pragma unroll
    for (int s = 0; s < 2; s++) {
#pragma unroll
        for (int h = 0; h < 2; h++) {
            const int row = m0 + wm * 32 + s * 16 + gid + h * 8;
            if (row < n) {
                const float di = g_dinv[row];
#pragma unroll
                for (int t = 0; t < 4; t++) {
                    const int col = wn * 32 + t * 8 + tig * 2;
                    const float vx = c[s][t][h * 2 + 0] * di;
                    const float vy = c[s][t][h * 2 + 1] * di;
                    g_half[(size_t)row * 32 + (col >> 1)] = __floats2half2_rn(vx, vy);
                }
            }
        }
    }
}

// ---------------------------------------------------------------------------
// 3) pull v2 (measured-best): one warp per node, HALF-WARP per source row,
//    uint2 per lane; float4 accumulator per lane per half; shfl_xor(16)
//    combine; lanes 0-15 write the node row.
// ---------------------------------------------------------------------------
__global__ __launch_bounds__(256) void pull_kernel(
    float* __restrict__ out, const float* __restrict__ bias, int n)
{
    const int warp = (blockIdx.x * 256 + threadIdx.x) >> 5;
    const int lane = threadIdx.x & 31;
    if (warp >= n) return;
    const int half = lane >> 4;       // 0 or 1
    const int hl   = lane & 15;       // lane in half

    const int start = g_row_start[warp];
    const int end   = g_row_start[warp + 1];

    const uint2* rows = (const uint2*)g_half;   // 16 uint2 (128 B) per row

    float4 acc = make_float4(0.f, 0.f, 0.f, 0.f);

    // self loop g[c] — half 0 only (avoid double count)
    if (half == 0) {
        uint2 raw = rows[(size_t)warp * 16 + hl];
        float2 a = __half22float2(*(__half2*)&raw.x);
        float2 b = __half22float2(*(__half2*)&raw.y);
        acc.x = a.x; acc.y = a.y; acc.z = b.x; acc.w = b.y;
    }

    for (int j = start; j < end; j += 32) {
        const int id  = (j + lane < end) ? g_csr_src[j + lane] : 0;
        const int cnt = min(32, end - j);
        for (int k = 0; k < cnt; k += 8) {
            uint2 raw[4];
#pragma unroll
            for (int u = 0; u < 4; u++) {
                const int idx = k + u * 2 + half;           // this half's edge
                const int src = __shfl_sync(0xffffffff, id, idx & 31);
                raw[u] = (idx < cnt) ? rows[(size_t)src * 16 + hl]
                                     : make_uint2(0u, 0u);
            }
#pragma unroll
            for (int u = 0; u < 4; u++) {
                float2 a = __half22float2(*(__half2*)&raw[u].x);
                float2 b = __half22float2(*(__half2*)&raw[u].y);
                acc.x += a.x; acc.y += a.y; acc.z += b.x; acc.w += b.y;
            }
        }
    }

    // combine the two halves
    acc.x += __shfl_xor_sync(0xffffffff, acc.x, 16);
    acc.y += __shfl_xor_sync(0xffffffff, acc.y, 16);
    acc.z += __shfl_xor_sync(0xffffffff, acc.z, 16);
    acc.w += __shfl_xor_sync(0xffffffff, acc.w, 16);

    if (half == 0) {
        const float di = g_dinv[warp];
        const float4 bb = ((const float4*)bias)[hl];
        float4 o;
        o.x = acc.x * di + bb.x;
        o.y = acc.y * di + bb.y;
        o.z = acc.z * di + bb.z;
        o.w = acc.w * di + bb.w;
        ((float4*)out)[(size_t)warp * 16 + hl] = o;
    }
}

// ---------------------------------------------------------------------------
extern "C" void kernel_launch(void* const* d_in, const int* in_sizes, int n_in,
                              void* d_out, int out_size)
{
    const float* x  = (const float*)d_in[0];
    const int*   ei = (const int*)d_in[1];     // int32 edge_index [2, E]
    const float* W  = (const float*)d_in[2];
    const float* b  = (const float*)d_in[3];
    float*       out = (float*)d_out;

    const int n = in_sizes[0] / IN_CH;   // 100000
    const int e = in_sizes[1] / 2;       // 1600000

    // one memset covers deg + scan_state (adjacent in the struct)
    void* p = nullptr;
    cudaGetSymbolAddress(&p, g_z);
    cudaMemsetAsync(p, 0, sizeof(ZeroBlock));

    count_deg_kernel<<<(e + 255) / 256, 256>>>(ei, e);

    const int nb = (n + 255) / 256;
    scan_kernel<<<nb, 256>>>(n);

    gemm_tc_kernel<<<(n + 127) / 128, 256>>>(x, W, n);

    fill_csr_kernel<<<(e + 255) / 256, 256>>>(ei, e);

    pull_kernel<<<(n * 32 + 255) / 256, 256>>>(out, b, n);
}